// round 6
// baseline (speedup 1.0000x reference)
#include <cuda_runtime.h>
#include <cuda_bf16.h>
#include <cstdint>

// Problem constants
constexpr int kN  = 50000;
constexpr int kE  = 800000;
constexpr int kM  = 4;
constexpr int kH  = 4;
constexpr int kC  = 32;
constexpr int kIN = 256;
constexpr int kD  = 128;
constexpr int kMN = kM * kN;
constexpr int kME = kM * kE;
constexpr int PAD = 64;

constexpr int NGEMM = (kN + 127) / 128;  // 391
constexpr int NBUK  = 1250;

constexpr int TILE_B   = 128 * 64;            // 8KB per bf16 tile (128 rows x 32 k x 2B)
constexpr int EPI_STR  = 129;                 // epilogue smem row stride (floats)
constexpr int SMEM_DYN = 128 * EPI_STR * 4 + 1024;  // 67072 (>= 4*TILE_B + pad)

// Scratch (__device__ globals; zero-initialized)
__device__ float         g_h[kN * kD];
__device__ unsigned      g_hpu[kN * 64];
__device__ float         g_adst[kMN * kH];
__device__ float         g_asrc[kMN * kH];
__device__ int           g_cnt[kMN];          // consumers reset to 0 after use
__device__ int           g_bsrc[(long)kMN * PAD];
__device__ __nv_bfloat16 g_Whi[kD * kIN];     // W transposed, hi part: [n][k]
__device__ __nv_bfloat16 g_Wlo[kD * kIN];     // W transposed, lo part: [n][k]

// ---------------------------------------------------------------------------
// helpers
// ---------------------------------------------------------------------------
__device__ __forceinline__ unsigned smem_u32(const void* p) {
    unsigned a;
    asm("{ .reg .u64 t; cvta.to.shared.u64 t, %1; cvt.u32.u64 %0, t; }"
        : "=r"(a) : "l"(p));
    return a;
}
__device__ __forceinline__ void ldsm4(unsigned* r, unsigned addr) {
    asm volatile("ldmatrix.sync.aligned.m8n8.x4.shared.b16 {%0,%1,%2,%3}, [%4];"
                 : "=r"(r[0]), "=r"(r[1]), "=r"(r[2]), "=r"(r[3])
                 : "r"(addr));
}
__device__ __forceinline__ void mma_bf16(float* d, const unsigned* a,
                                         const unsigned* b) {
    asm volatile(
        "mma.sync.aligned.m16n8k16.row.col.f32.bf16.bf16.f32 "
        "{%0,%1,%2,%3}, {%4,%5,%6,%7}, {%8,%9}, {%0,%1,%2,%3};"
        : "+f"(d[0]), "+f"(d[1]), "+f"(d[2]), "+f"(d[3])
        : "r"(a[0]), "r"(a[1]), "r"(a[2]), "r"(a[3]), "r"(b[0]), "r"(b[1]));
}
// swizzled byte offset of 16B granule (row, g) in a [rows][32] bf16 tile
__device__ __forceinline__ unsigned swz(int row, int g) {
    return (unsigned)(row * 64 + (((g ^ (row >> 1)) & 3) << 4));
}
__device__ __forceinline__ unsigned b2u(__nv_bfloat162 v) {
    return *(unsigned*)&v;
}

// ---------------------------------------------------------------------------
// K0: split W into bf16 hi/lo, transposed to [n][k]
// ---------------------------------------------------------------------------
__global__ void k_prep(const float* __restrict__ W)
{
    int n = blockIdx.x;        // 0..127
    int k = threadIdx.x;       // 0..255
    float v = W[(long)k * kD + n];
    __nv_bfloat16 hi = __float2bfloat16_rn(v);
    __nv_bfloat16 lo = __float2bfloat16_rn(v - __bfloat162float(hi));
    g_Whi[n * kIN + k] = hi;
    g_Wlo[n * kIN + k] = lo;
}

// ---------------------------------------------------------------------------
// K1: heterogeneous. GEMM blocks: h = relu(feats@W + b) via mma.sync bf16
// split-precision (hi*hi + hi*lo + lo*hi, fp32 accum). Epilogue via smem:
// writes g_h, packed g_hpu, fused alpha terms. Other blocks: bucket build.
// ---------------------------------------------------------------------------
__global__ __launch_bounds__(256)
void k_fused(const float* __restrict__ A, const float* __restrict__ bias,
             const int* __restrict__ ei, const float* __restrict__ attn)
{
    extern __shared__ char dyns[];
    __shared__ float at[kM * kH * 2 * kC];   // 1024
    __shared__ float sbias[kD];

    if (blockIdx.x >= NGEMM) {
        // ---- bucket build ----
        int t = (blockIdx.x - NGEMM) * 256 + threadIdx.x;
        const int stride = NBUK * 256;
        for (; t < kME; t += stride) {
            int m   = t / kE;
            int e   = t - m * kE;
            int src = ei[(m * 2 + 0) * kE + e];
            int dst = ei[(m * 2 + 1) * kE + e];
            int row = m * kN + dst;
            int pos = atomicAdd(&g_cnt[row], 1);
            if (pos < PAD) g_bsrc[(long)row * PAD + pos] = src;
        }
        return;
    }

    const int tid  = threadIdx.x;
    const int lane = tid & 31;
    const int w    = tid >> 5;      // 0..7
    const int wm   = w >> 1;        // 0..3 -> rows wm*32
    const int wn   = w & 1;         // 0..1 -> cols wn*64
    const int rowBase = blockIdx.x * 128;

    // 1024-aligned dyn smem carve
    unsigned dbase = smem_u32(dyns);
    unsigned abase = (dbase + 1023u) & ~1023u;
    char* pbase = dyns + (abase - dbase);
    char* pAhi = pbase;
    char* pAlo = pbase + TILE_B;
    char* pBhi = pbase + 2 * TILE_B;
    char* pBlo = pbase + 3 * TILE_B;
    const unsigned uAhi = abase, uAlo = abase + TILE_B;
    const unsigned uBhi = abase + 2 * TILE_B, uBlo = abase + 3 * TILE_B;
    float* epi = (float*)pbase;

#pragma unroll
    for (int i = 0; i < 4; i++) at[tid + i * 256] = attn[tid + i * 256];
    if (tid < kD) sbias[tid] = bias[tid];

    float d[2][8][4];
#pragma unroll
    for (int mt = 0; mt < 2; mt++)
#pragma unroll
        for (int nt = 0; nt < 8; nt++)
#pragma unroll
            for (int i = 0; i < 4; i++) d[mt][nt][i] = 0.f;

    for (int c = 0; c < 8; c++) {
        const int kb = c * 32;
        // ---- fill A hi/lo (128 rows x 32 k), 2 granules per thread ----
#pragma unroll
        for (int i = 0; i < 2; i++) {
            int idx = tid + i * 256;            // 0..511
            int r   = idx >> 2;
            int g   = idx & 3;
            int gr  = rowBase + r;
            float4 v0 = make_float4(0.f, 0.f, 0.f, 0.f);
            float4 v1 = make_float4(0.f, 0.f, 0.f, 0.f);
            if (gr < kN) {
                const float* ap = A + (long)gr * kIN + kb + g * 8;
                v0 = *(const float4*)ap;
                v1 = *(const float4*)(ap + 4);
            }
            __nv_bfloat162 h0 = __floats2bfloat162_rn(v0.x, v0.y);
            __nv_bfloat162 h1 = __floats2bfloat162_rn(v0.z, v0.w);
            __nv_bfloat162 h2 = __floats2bfloat162_rn(v1.x, v1.y);
            __nv_bfloat162 h3 = __floats2bfloat162_rn(v1.z, v1.w);
            __nv_bfloat162 l0 = __floats2bfloat162_rn(
                v0.x - __bfloat162float(h0.x), v0.y - __bfloat162float(h0.y));
            __nv_bfloat162 l1 = __floats2bfloat162_rn(
                v0.z - __bfloat162float(h1.x), v0.w - __bfloat162float(h1.y));
            __nv_bfloat162 l2 = __floats2bfloat162_rn(
                v1.x - __bfloat162float(h2.x), v1.y - __bfloat162float(h2.y));
            __nv_bfloat162 l3 = __floats2bfloat162_rn(
                v1.z - __bfloat162float(h3.x), v1.w - __bfloat162float(h3.y));
            unsigned off = swz(r, g);
            *(uint4*)(pAhi + off) = make_uint4(b2u(h0), b2u(h1), b2u(h2), b2u(h3));
            *(uint4*)(pAlo + off) = make_uint4(b2u(l0), b2u(l1), b2u(l2), b2u(l3));
        }
        // ---- fill B hi/lo from pre-split W^T: pure granule copies ----
#pragma unroll
        for (int i = 0; i < 2; i++) {
            int idx = tid + i * 256;
            int n   = idx >> 2;
            int g   = idx & 3;
            unsigned off = swz(n, g);
            long gb = (long)n * (kIN * 2) + (kb + g * 8) * 2;  // bytes
            *(uint4*)(pBhi + off) = *(const uint4*)((const char*)g_Whi + gb);
            *(uint4*)(pBlo + off) = *(const uint4*)((const char*)g_Wlo + gb);
        }
        __syncthreads();

        // ---- HMMA ----
#pragma unroll
        for (int ks = 0; ks < 2; ks++) {
            const int g = ks * 2;
            unsigned Bh[16], Bl[16];
#pragma unroll
            for (int ntp = 0; ntp < 4; ntp++) {
                int n0  = wn * 64 + ntp * 16;
                int row = n0 + ((lane & 7) | ((lane & 16) >> 1));
                int g2  = g + ((lane >> 3) & 1);
                unsigned off = swz(row, g2);
                ldsm4(&Bh[ntp * 4], uBhi + off);
                ldsm4(&Bl[ntp * 4], uBlo + off);
            }
#pragma unroll
            for (int mt = 0; mt < 2; mt++) {
                int r0  = wm * 32 + mt * 16;
                int row = r0 + ((lane & 7) | (lane & 8));
                int g2  = g + (lane >> 4);
                unsigned off = swz(row, g2);
                unsigned Ah[4], Al[4];
                ldsm4(Ah, uAhi + off);
                ldsm4(Al, uAlo + off);
#pragma unroll
                for (int nt = 0; nt < 8; nt++) {
                    mma_bf16(d[mt][nt], Ah, &Bh[nt * 2]);
                    mma_bf16(d[mt][nt], Ah, &Bl[nt * 2]);
                    mma_bf16(d[mt][nt], Al, &Bh[nt * 2]);
                }
            }
        }
        __syncthreads();
    }

    // ---- dump accumulators to smem ----
#pragma unroll
    for (int mt = 0; mt < 2; mt++) {
#pragma unroll
        for (int nt = 0; nt < 8; nt++) {
            int r = wm * 32 + mt * 16 + (lane >> 2);
            int cc = wn * 64 + nt * 8 + (lane & 3) * 2;
            epi[r * EPI_STR + cc]           = d[mt][nt][0];
            epi[r * EPI_STR + cc + 1]       = d[mt][nt][1];
            epi[(r + 8) * EPI_STR + cc]     = d[mt][nt][2];
            epi[(r + 8) * EPI_STR + cc + 1] = d[mt][nt][3];
        }
    }
    __syncthreads();

    // ---- per-row epilogue (threads 0..127) ----
    if (tid < 128) {
        const int r  = tid;
        const int gr = rowBase + r;
        const bool valid = (gr < kN);
        unsigned* up = g_hpu + (long)gr * 64;
#pragma unroll
        for (int g = 0; g < 4; g++) {      // head g = cols 32g..32g+31
            float o[32];
#pragma unroll
            for (int j = 0; j < 32; j++)
                o[j] = fmaxf(epi[r * EPI_STR + g * 32 + j] + sbias[g * 32 + j],
                             0.f);
            if (valid) {
#pragma unroll
                for (int j = 0; j < 8; j++)
                    *(float4*)(g_h + (long)gr * kD + g * 32 + 4 * j) =
                        *(float4*)(o + 4 * j);
#pragma unroll
                for (int j = 0; j < 16; j++) {
                    int cch = g * 32 + 2 * j;
                    int ui  = (cch < 64) ? cch : (cch - 63);
                    __nv_bfloat162 p =
                        __floats2bfloat162_rn(o[2 * j], o[2 * j + 1]);
                    up[ui] = b2u(p);
                }
            }
#pragma unroll
            for (int m = 0; m < kM; m++) {
                const float* am = at + (m * kH + g) * (2 * kC);
                float dl = 0.f, drr = 0.f;
#pragma unroll
                for (int j = 0; j < 32; j++) {
                    dl  = fmaf(o[j], am[j], dl);
                    drr = fmaf(o[j], am[kC + j], drr);
                }
                if (valid) {
                    g_adst[((long)m * kN + gr) * kH + g] = dl;
                    g_asrc[((long)m * kN + gr) * kH + g] = drr;
                }
            }
        }
    }
}

// ---------------------------------------------------------------------------
// K3: fused aggregation + relation attention. Warp per node.
// Reads g_cnt once and resets it to 0 (keeps replay invariant, kills k_zero).
// ---------------------------------------------------------------------------
__global__ __launch_bounds__(256, 5) void k_aggbeta(
    const float* __restrict__ ral, const float* __restrict__ rar,
    const float* __restrict__ rbias, float* __restrict__ outp)
{
    __shared__ int    ssh[8][PAD];
    __shared__ float2 wsh[8][PAD][2];
    __shared__ float4 sera[8][kM][32];
    const int w    = threadIdx.x >> 5;
    const int lane = threadIdx.x & 31;
    const int q    = lane >> 4;
    const int n    = blockIdx.x * 8 + w;
    if (n >= kN) return;

    const uint2* __restrict__ hp = (const uint2*)g_hpu + lane;

    for (int m = 0; m < kM; m++) {
        const int row = m * kN + n;
        const float4 ad = *(const float4*)(g_adst + (long)row * 4);
        int cnt0 = 0;
        if (lane == 0) { cnt0 = g_cnt[row]; g_cnt[row] = 0; }
        cnt0 = __shfl_sync(0xffffffffu, cnt0, 0);
        const int cnt = min(cnt0, PAD);
        const int* __restrict__ bl = g_bsrc + (long)row * PAD;

        for (int b = lane; b < cnt; b += 32) {
            int s = bl[b];
            float4 as = *(const float4*)(g_asrc + (long)(m * kN + s) * 4);
            float l0 = ad.x + as.x; l0 = l0 > 0.f ? l0 : 0.2f * l0;
            float l1 = ad.y + as.y; l1 = l1 > 0.f ? l1 : 0.2f * l1;
            float l2 = ad.z + as.z; l2 = l2 > 0.f ? l2 : 0.2f * l2;
            float l3 = ad.w + as.w; l3 = l3 > 0.f ? l3 : 0.2f * l3;
            ssh[w][b]    = s;
            wsh[w][b][0] = make_float2(__expf(l0), __expf(l2));
            wsh[w][b][1] = make_float2(__expf(l1), __expf(l3));
        }
        __syncwarp();

        float2 a0 = make_float2(0.f, 0.f), a1 = make_float2(0.f, 0.f);
        float d0 = 0.f, d1 = 0.f;
        int jb = 0;
        for (; jb + 8 <= cnt; jb += 8) {
            uint2 v[8];
#pragma unroll
            for (int k = 0; k < 8; k++) {
                int s = ssh[w][jb + k];
                v[k] = hp[(long)s * 32];
            }
#pragma unroll
            for (int k = 0; k < 8; k++) {
                const float2 t = wsh[w][jb + k][q];
                const float f0 = __int_as_float(v[k].x << 16);
                const float f1 = __int_as_float(v[k].x & 0xffff0000u);
                const float f2 = __int_as_float(v[k].y << 16);
                const float f3 = __int_as_float(v[k].y & 0xffff0000u);
                a0.x = fmaf(t.x, f0, a0.x); a0.y = fmaf(t.x, f1, a0.y);
                a1.x = fmaf(t.y, f2, a1.x); a1.y = fmaf(t.y, f3, a1.y);
                d0 += t.x; d1 += t.y;
            }
        }
        for (; jb < cnt; jb++) {
            int s = ssh[w][jb];
            uint2 v = hp[(long)s * 32];
            const float2 t = wsh[w][jb][q];
            const float f0 = __int_as_float(v.x << 16);
            const float f1 = __int_as_float(v.x & 0xffff0000u);
            const float f2 = __int_as_float(v.y << 16);
            const float f3 = __int_as_float(v.y & 0xffff0000u);
            a0.x = fmaf(t.x, f0, a0.x); a0.y = fmaf(t.x, f1, a0.y);
            a1.x = fmaf(t.y, f2, a1.x); a1.y = fmaf(t.y, f3, a1.y);
            d0 += t.x; d1 += t.y;
        }
        const float i0 = 1.f / (d0 + 1e-16f);
        const float i1 = 1.f / (d1 + 1e-16f);
        sera[w][m][lane] = make_float4(a0.x * i0, a0.y * i0,
                                       a1.x * i1, a1.y * i1);
        __syncwarp();
    }

    // ---- beta phase ----
    const int h0 = q;
    const int h1 = 2 + q;
    const int cc = (2 * lane) & 31;

    const float2 ha  = *(const float2*)(g_h + (long)n * kD + 2 * lane);
    const float2 hbv = *(const float2*)(g_h + (long)n * kD + 64 + 2 * lane);

    float2 era[5], erb[5];
#pragma unroll
    for (int r = 0; r < 4; r++) {
        float4 t = sera[w][r][lane];
        era[r] = make_float2(t.x, t.y);
        erb[r] = make_float2(t.z, t.w);
    }
    era[4] = ha;
    erb[4] = hbv;

    float bta[5], btb[5];
    const float2 rla = *(const float2*)(ral + h0 * kC + cc);
    const float2 rlb = *(const float2*)(ral + h1 * kC + cc);
    const float2 bla = make_float2(fmaxf(ha.x * rla.x, 0.f),
                                   fmaxf(ha.y * rla.y, 0.f));
    const float2 blb = make_float2(fmaxf(hbv.x * rlb.x, 0.f),
                                   fmaxf(hbv.y * rlb.y, 0.f));
#pragma unroll
    for (int r = 0; r < 5; r++) {
        const float2 rra = *(const float2*)(rar + ((r * kH + h0) * kC + cc));
        const float2 rrb = *(const float2*)(rar + ((r * kH + h1) * kC + cc));
        float bax = fmaxf(era[r].x * rra.x, 0.f);
        float bay = fmaxf(era[r].y * rra.y, 0.f);
        float bbx = fmaxf(erb[r].x * rrb.x, 0.f);
        float bby = fmaxf(erb[r].y * rrb.y, 0.f);
        float p0 = bla.x * bax + bla.y * bay;
        float p1 = blb.x * bbx + blb.y * bby;
#pragma unroll
        for (int o = 8; o > 0; o >>= 1) {
            p0 += __shfl_xor_sync(0xffffffffu, p0, o);
            p1 += __shfl_xor_sync(0xffffffffu, p1, o);
        }
        bta[r] = p0 + rbias[r];
        btb[r] = p1 + rbias[r];
    }
    float m0 = bta[0], m1 = btb[0];
#pragma unroll
    for (int r = 1; r < 5; r++) { m0 = fmaxf(m0, bta[r]); m1 = fmaxf(m1, btb[r]); }
    float s0 = 0.f, s1 = 0.f, e0[5], e1[5];
#pragma unroll
    for (int r = 0; r < 5; r++) {
        e0[r] = expf(bta[r] - m0); s0 += e0[r];
        e1[r] = expf(btb[r] - m1); s1 += e1[r];
    }
    const float is0 = 1.f / s0, is1 = 1.f / s1;
    float2 oa = make_float2(0.f, 0.f), ob = make_float2(0.f, 0.f);
#pragma unroll
    for (int r = 0; r < 5; r++) {
        const float w0 = e0[r] * is0, w1 = e1[r] * is1;
        oa.x = fmaf(w0, era[r].x, oa.x); oa.y = fmaf(w0, era[r].y, oa.y);
        ob.x = fmaf(w1, erb[r].x, ob.x); ob.y = fmaf(w1, erb[r].y, ob.y);
    }
    oa.x = fmaxf(oa.x, 0.f); oa.y = fmaxf(oa.y, 0.f);
    ob.x = fmaxf(ob.x, 0.f); ob.y = fmaxf(ob.y, 0.f);
    *(float2*)(outp + (long)n * kD + 2 * lane)      = oa;
    *(float2*)(outp + (long)n * kD + 64 + 2 * lane) = ob;
}

// ---------------------------------------------------------------------------
extern "C" void kernel_launch(void* const* d_in, const int* in_sizes, int n_in,
                              void* d_out, int out_size)
{
    const float* feats = (const float*)d_in[0];
    const int*   ei    = (const int*)d_in[1];
    const float* W     = (const float*)d_in[2];
    const float* b     = (const float*)d_in[3];
    const float* attn  = (const float*)d_in[4];
    const float* ral   = (const float*)d_in[5];
    const float* rar   = (const float*)d_in[6];
    const float* rbias = (const float*)d_in[7];
    float* outp = (float*)d_out;

    cudaFuncSetAttribute(k_fused, cudaFuncAttributeMaxDynamicSharedMemorySize,
                         SMEM_DYN);
    k_prep<<<kD, kIN>>>(W);
    k_fused<<<NGEMM + NBUK, 256, SMEM_DYN>>>(feats, b, ei, attn);
    k_aggbeta<<<(kN + 7) / 8, 256>>>(ral, rar, rbias, outp);
}